// round 2
// baseline (speedup 1.0000x reference)
#include <cuda_runtime.h>
#include <cuda_bf16.h>
#include <math.h>

// Problem shape: predictions [16,1,512,512] f32, targets [16,1,512,512] i32,
// output scalar f32.
#define NIMG 16
#define H 512
#define W 512
#define NPIX (NIMG * H * W)

// Scratch (static device arrays — no allocation).
// g_g2[0] = squared 1D x-distance to nearest BACKGROUND pixel (sites = ~mask)
// g_g2[1] = squared 1D x-distance to nearest FOREGROUND pixel (sites = mask)
__device__ float g_g2[2][NIMG][H][W];
__device__ double g_part[2048][4];
__device__ int g_fg[NIMG];

__global__ void k_init() {
    if (threadIdx.x < NIMG) g_fg[threadIdx.x] = 0;
}

// One warp per (img,row). Exact 1D distance along W via min-plus scans:
//   fwd[i] = x_i + cummin_{j<=i}(pen_j - x_j),  bwd[i] = -x_i + revcummin(pen_j + x_j)
//   g = min(fwd,bwd); store g*g for both site sets.
__global__ void k_rowpass(const int* __restrict__ tg) {
    const int warp = threadIdx.x >> 5, lane = threadIdx.x & 31;
    const int rowGlobal = blockIdx.x * 8 + warp;     // 0..8191
    const int img = rowGlobal >> 9;
    const unsigned FULL = 0xFFFFFFFFu;

    const int* trow = tg + (size_t)rowGlobal * W;
    int tvs[16];
    int any = 0;
#pragma unroll
    for (int c = 0; c < 16; c++) { tvs[c] = trow[c * 32 + lane]; any |= tvs[c]; }
    if (__any_sync(FULL, any) && lane == 0) g_fg[img] = 1;

    const float INFP = 1000000.0f;
    float fb[16], ff[16];
    float carry_b = 3.0e30f, carry_f = 3.0e30f;
    // forward pass
#pragma unroll
    for (int c = 0; c < 16; c++) {
        float fx = (float)(c * 32 + lane);
        float vb = (tvs[c] ? INFP : 0.0f) - fx;   // sites = background (t==0)
        float vf = (tvs[c] ? 0.0f : INFP) - fx;   // sites = foreground (t==1)
#pragma unroll
        for (int o = 1; o < 32; o <<= 1) {
            float nb = __shfl_up_sync(FULL, vb, o);
            float nf = __shfl_up_sync(FULL, vf, o);
            if (lane >= o) { vb = fminf(vb, nb); vf = fminf(vf, nf); }
        }
        vb = fminf(vb, carry_b); vf = fminf(vf, carry_f);
        carry_b = __shfl_sync(FULL, vb, 31);
        carry_f = __shfl_sync(FULL, vf, 31);
        fb[c] = fx + vb; ff[c] = fx + vf;
    }
    // backward pass + write g^2
    carry_b = 3.0e30f; carry_f = 3.0e30f;
    float* outb = &g_g2[0][0][0][0] + (size_t)rowGlobal * W;
    float* outf = &g_g2[1][0][0][0] + (size_t)rowGlobal * W;
#pragma unroll
    for (int c = 15; c >= 0; c--) {
        float fx = (float)(c * 32 + lane);
        float vb = (tvs[c] ? INFP : 0.0f) + fx;
        float vf = (tvs[c] ? 0.0f : INFP) + fx;
#pragma unroll
        for (int o = 1; o < 32; o <<= 1) {
            float nb = __shfl_down_sync(FULL, vb, o);
            float nf = __shfl_down_sync(FULL, vf, o);
            if (lane + o < 32) { vb = fminf(vb, nb); vf = fminf(vf, nf); }
        }
        vb = fminf(vb, carry_b); vf = fminf(vf, carry_f);
        carry_b = __shfl_sync(FULL, vb, 0);
        carry_f = __shfl_sync(FULL, vf, 0);
        float gb = fminf(fb[c], vb - fx);
        float gf = fminf(ff[c], vf - fx);
        outb[c * 32 + lane] = gb * gb;
        outf[c * 32 + lane] = gf * gf;
    }
}

// Column envelope with exact early-out window, fused with sigmoid + partial sums.
// Block: (32 x, 8 y-threads), each thread handles 8 consecutive y.
// Grid: (W/32, H/64, NIMG) = (16, 8, 16) = 2048 blocks.
__global__ void k_colpass(const float* __restrict__ pred, const int* __restrict__ tg) {
    const int x = blockIdx.x * 32 + threadIdx.x;
    const int img = blockIdx.z;
    const int ybase = blockIdx.y * 64 + threadIdx.y * 8;
    const float* __restrict__ g2b = &g_g2[0][img][0][0];
    const float* __restrict__ g2f = &g_g2[1][img][0][0];
    const size_t base = (size_t)img * H * W;
    const int fg = g_fg[img];

    double s0 = 0.0, s1 = 0.0, s2 = 0.0, s3 = 0.0; // sum_p, inter, sum_t, sum_phi_p
#pragma unroll
    for (int k = 0; k < 8; k++) {
        int y = ybase + k;
        int idx = y * W + x;
        int tv = tg[base + idx];
        float pv = pred[base + idx];
        float p = 1.0f / (1.0f + __expf(-pv));
        const float* __restrict__ col = tv ? g2b : g2f;
        float best = col[idx];
        for (int dy = 1; dy < H; ++dy) {
            float dy2 = (float)(dy * dy);
            if (dy2 >= best) break;
            int yu = y - dy, yd = y + dy;
            if (yu >= 0) best = fminf(best, col[yu * W + x] + dy2);
            if (yd < H)  best = fminf(best, col[yd * W + x] + dy2);
        }
        float phi = sqrtf(best);
        if (tv) phi = -phi;
        if (!fg || fabsf(phi) > 100000.0f) phi = 0.0f;
        s0 += (double)p;
        if (tv) s1 += (double)p;
        s2 += (double)tv;
        s3 += (double)phi * (double)p;
    }

    __shared__ double sh[4][256];
    const int tid = threadIdx.y * 32 + threadIdx.x;
    sh[0][tid] = s0; sh[1][tid] = s1; sh[2][tid] = s2; sh[3][tid] = s3;
    __syncthreads();
    for (int o = 128; o > 0; o >>= 1) {
        if (tid < o) {
            sh[0][tid] += sh[0][tid + o];
            sh[1][tid] += sh[1][tid + o];
            sh[2][tid] += sh[2][tid + o];
            sh[3][tid] += sh[3][tid + o];
        }
        __syncthreads();
    }
    if (tid == 0) {
        int bid = (blockIdx.z * gridDim.y + blockIdx.y) * gridDim.x + blockIdx.x;
        g_part[bid][0] = sh[0][0];
        g_part[bid][1] = sh[1][0];
        g_part[bid][2] = sh[2][0];
        g_part[bid][3] = sh[3][0];
    }
}

__global__ void k_final(float* __restrict__ out) {
    __shared__ double sh[4][256];
    const int tid = threadIdx.x;
    double a0 = 0.0, a1 = 0.0, a2 = 0.0, a3 = 0.0;
    for (int i = tid; i < 2048; i += 256) {
        a0 += g_part[i][0]; a1 += g_part[i][1];
        a2 += g_part[i][2]; a3 += g_part[i][3];
    }
    sh[0][tid] = a0; sh[1][tid] = a1; sh[2][tid] = a2; sh[3][tid] = a3;
    __syncthreads();
    for (int o = 128; o > 0; o >>= 1) {
        if (tid < o) {
            sh[0][tid] += sh[0][tid + o];
            sh[1][tid] += sh[1][tid + o];
            sh[2][tid] += sh[2][tid + o];
            sh[3][tid] += sh[3][tid + o];
        }
        __syncthreads();
    }
    if (tid == 0) {
        double sum_p = sh[0][0], inter = sh[1][0], sum_t = sh[2][0], sum_b = sh[3][0];
        double smooth = 1e-06;
        double dice = 1.0 - (2.0 * inter + smooth) / (sum_p + sum_t + smooth);
        double boundary = sum_b / (double)NPIX;
        double alpha = 0.01;
        out[0] = (float)((1.0 - alpha) * dice + alpha * boundary);
    }
}

extern "C" void kernel_launch(void* const* d_in, const int* in_sizes, int n_in,
                              void* d_out, int out_size) {
    const float* pred = (const float*)d_in[0];
    const int*   targ = (const int*)d_in[1];
    float* out = (float*)d_out;

    k_init<<<1, 32>>>();
    // 16 imgs * 512 rows = 8192 rows, 8 warps (rows) per block
    k_rowpass<<<1024, 256>>>(targ);
    dim3 cb(32, 8, 1);
    dim3 cg(W / 32, H / 64, NIMG);
    k_colpass<<<cg, cb>>>(pred, targ);
    k_final<<<1, 256>>>(out);
}

// round 3
// speedup vs baseline: 1.0507x; 1.0507x over previous
#include <cuda_runtime.h>
#include <cuda_bf16.h>
#include <math.h>

// predictions [16,1,512,512] f32, targets [16,1,512,512] i32, output scalar f32.
#define NIMG 16
#define H 512
#define W 512
#define NPIX (NIMG * H * W)
#define NBLK 2048          // colpass block count
#define IINF (1 << 20)

// Packed per-pixel word: bits[0:16)=gb (dist to nearest BG site, clamped 1024),
// bits[16:31)=gf (dist to nearest FG site, clamped 1024), bit31 = target.
__device__ unsigned g_pk[NIMG * H * W];
__device__ double g_part[NBLK][5];
__device__ int g_ticket;

// One warp per row; each thread owns 16 CONTIGUOUS pixels.
// Local sequential min-plus cummin + single warp scan over lane carries.
__global__ void k_rowpass(const int* __restrict__ tg) {
    if (blockIdx.x == 0 && threadIdx.x == 0) g_ticket = 0;
    const int warp = threadIdx.x >> 5, lane = threadIdx.x & 31;
    const int row = blockIdx.x * 4 + warp;           // 8192 rows total
    const unsigned FULL = 0xFFFFFFFFu;

    const int4* tr = (const int4*)(tg + (size_t)row * W) + lane * 4;
    int m = 0;  // 16-bit mask of targets for this thread's pixels
    {
        int4 a = tr[0], b4 = tr[1], c = tr[2], d = tr[3];
        int v[16] = {a.x, a.y, a.z, a.w, b4.x, b4.y, b4.z, b4.w,
                     c.x, c.y, c.z, c.w, d.x, d.y, d.z, d.w};
#pragma unroll
        for (int j = 0; j < 16; j++) m |= (v[j] != 0) << j;
    }
    const int pbase = lane * 16;

    // forward: F[i] = i + cummin(s? -i : INF)
    int laf[16], lab[16];             // fg-sites, bg-sites local inclusive cummin
    int rf = IINF, rb = IINF;
#pragma unroll
    for (int j = 0; j < 16; j++) {
        int p = pbase + j;
        int bit = (m >> j) & 1;
        rf = min(rf, bit ? -p : IINF);
        rb = min(rb, bit ? IINF : -p);
        laf[j] = rf; lab[j] = rb;
    }
    int vf = rf, vb = rb;
#pragma unroll
    for (int o = 1; o < 32; o <<= 1) {
        int nf = __shfl_up_sync(FULL, vf, o);
        int nb = __shfl_up_sync(FULL, vb, o);
        if (lane >= o) { vf = min(vf, nf); vb = min(vb, nb); }
    }
    int ef = __shfl_up_sync(FULL, vf, 1); if (lane == 0) ef = IINF;
    int eb = __shfl_up_sync(FULL, vb, 1); if (lane == 0) eb = IINF;
#pragma unroll
    for (int j = 0; j < 16; j++) {
        int p = pbase + j;
        laf[j] = p + min(laf[j], ef);   // F for fg-sites
        lab[j] = p + min(lab[j], eb);   // F for bg-sites
    }

    // backward: B[i] = -i + revcummin(s? i : INF)
    int lbf[16], lbb[16];
    rf = IINF; rb = IINF;
#pragma unroll
    for (int j = 15; j >= 0; j--) {
        int p = pbase + j;
        int bit = (m >> j) & 1;
        rf = min(rf, bit ? p : IINF);
        rb = min(rb, bit ? IINF : p);
        lbf[j] = rf; lbb[j] = rb;
    }
    vf = rf; vb = rb;
#pragma unroll
    for (int o = 1; o < 32; o <<= 1) {
        int nf = __shfl_down_sync(FULL, vf, o);
        int nb = __shfl_down_sync(FULL, vb, o);
        if (lane + o < 32) { vf = min(vf, nf); vb = min(vb, nb); }
    }
    ef = __shfl_down_sync(FULL, vf, 1); if (lane == 31) ef = IINF;
    eb = __shfl_down_sync(FULL, vb, 1); if (lane == 31) eb = IINF;

    unsigned* outp = g_pk + (size_t)row * W + pbase;
#pragma unroll
    for (int q = 0; q < 4; q++) {
        unsigned tmp[4];
#pragma unroll
        for (int jj = 0; jj < 4; jj++) {
            int j = q * 4 + jj;
            int p = pbase + j;
            int Bf = -p + min(lbf[j], ef);
            int Bb = -p + min(lbb[j], eb);
            int gf = min(min(laf[j], Bf), 1024);
            int gb = min(min(lab[j], Bb), 1024);
            unsigned bit = (unsigned)((m >> j) & 1);
            tmp[jj] = (unsigned)gb | ((unsigned)gf << 16) | (bit << 31);
        }
        uint4 wv; wv.x = tmp[0]; wv.y = tmp[1]; wv.z = tmp[2]; wv.w = tmp[3];
        ((uint4*)outp)[q] = wv;
    }
}

// Column envelope (exact, early-break) + sigmoid + all partial sums,
// with the grid-final reduction fused via last-block ticket.
__global__ void k_colpass(const float* __restrict__ pred, float* __restrict__ out) {
    const int x = blockIdx.x * 32 + threadIdx.x;
    const int img = blockIdx.z;
    const int ybase = blockIdx.y * 64 + threadIdx.y * 8;
    const unsigned* __restrict__ base = g_pk + (size_t)img * H * W;
    const unsigned* __restrict__ colp = base + x;

    double s0 = 0, s1 = 0, s2 = 0, s3n = 0, s3p = 0;
#pragma unroll
    for (int k = 0; k < 8; k++) {
        int y = ybase + k;
        unsigned w = base[y * W + x];
        int tv = (int)(w >> 31);
        int g0 = tv ? (int)(w & 0xFFFFu) : (int)((w >> 16) & 0x7FFFu);
        float best = (float)(g0 * g0);
        for (int dy = 1; dy < H; ++dy) {
            float dy2 = (float)(dy * dy);
            if (dy2 >= best) break;
            int yu = y - dy, yd = y + dy;
            if (yu >= 0) {
                unsigned wu = colp[yu * W];
                int g = tv ? (int)(wu & 0xFFFFu) : (int)((wu >> 16) & 0x7FFFu);
                best = fminf(best, (float)(g * g) + dy2);
            }
            if (yd < H) {
                unsigned wd = colp[yd * W];
                int g = tv ? (int)(wd & 0xFFFFu) : (int)((wd >> 16) & 0x7FFFu);
                best = fminf(best, (float)(g * g) + dy2);
            }
        }
        float pv = pred[(size_t)img * H * W + y * W + x];
        float p = 1.0f / (1.0f + __expf(-pv));
        float phi = sqrtf(best);
        s0 += (double)p;
        s2 += (double)tv;
        if (tv) { s1 += (double)p; s3n -= (double)phi * (double)p; }
        else    { s3p += (double)phi * (double)p; }
    }

    __shared__ double sh[5][256];
    const int tid = threadIdx.y * 32 + threadIdx.x;
    sh[0][tid] = s0; sh[1][tid] = s1; sh[2][tid] = s2; sh[3][tid] = s3n; sh[4][tid] = s3p;
    __syncthreads();
    for (int o = 128; o > 0; o >>= 1) {
        if (tid < o) {
#pragma unroll
            for (int q = 0; q < 5; q++) sh[q][tid] += sh[q][tid + o];
        }
        __syncthreads();
    }

    const int bid = (blockIdx.z * gridDim.y + blockIdx.y) * gridDim.x + blockIdx.x;
    __shared__ int slast;
    if (tid == 0) {
#pragma unroll
        for (int q = 0; q < 5; q++) g_part[bid][q] = sh[q][0];
        __threadfence();
        slast = (atomicAdd(&g_ticket, 1) == NBLK - 1);
    }
    __syncthreads();
    if (!slast) return;
    __threadfence();

    // ---- last block: deterministic final reduction ----
    __shared__ double simg[NIMG];     // per-image sum_t (gates)
    const int wid = tid >> 5, lane = tid & 31;
#pragma unroll
    for (int t = 0; t < 2; t++) {
        int im = wid * 2 + t;
        double s = 0;
        for (int e = lane; e < 128; e += 32) s += g_part[im * 128 + e][2];
#pragma unroll
        for (int o = 16; o > 0; o >>= 1) s += __shfl_down_sync(0xFFFFFFFFu, s, o);
        if (lane == 0) simg[im] = s;
    }
    __syncthreads();

    double a0 = 0, a1 = 0, a2 = 0, a3 = 0;
    for (int e = tid; e < NBLK; e += 256) {
        int im = e >> 7;
        double st = simg[im];
        bool anyfg = st > 0.0;
        bool anybg = st < (double)(H * W);
        a0 += g_part[e][0]; a1 += g_part[e][1]; a2 += g_part[e][2];
        if (anyfg) a3 += g_part[e][4] + (anybg ? g_part[e][3] : 0.0);
    }
    sh[0][tid] = a0; sh[1][tid] = a1; sh[2][tid] = a2; sh[3][tid] = a3;
    __syncthreads();
    for (int o = 128; o > 0; o >>= 1) {
        if (tid < o) {
#pragma unroll
            for (int q = 0; q < 4; q++) sh[q][tid] += sh[q][tid + o];
        }
        __syncthreads();
    }
    if (tid == 0) {
        double sum_p = sh[0][0], inter = sh[1][0], sum_t = sh[2][0], sb = sh[3][0];
        double smooth = 1e-06;
        double dice = 1.0 - (2.0 * inter + smooth) / (sum_p + sum_t + smooth);
        double loss = 0.99 * dice + 0.01 * (sb / (double)NPIX);
        out[0] = (float)loss;
    }
}

extern "C" void kernel_launch(void* const* d_in, const int* in_sizes, int n_in,
                              void* d_out, int out_size) {
    const float* pred = (const float*)d_in[0];
    const int*   targ = (const int*)d_in[1];
    float* out = (float*)d_out;

    // 8192 rows, 4 warps (rows) per 128-thread block
    k_rowpass<<<2048, 128>>>(targ);
    dim3 cb(32, 8, 1);
    dim3 cg(W / 32, H / 64, NIMG);   // 2048 blocks
    k_colpass<<<cg, cb>>>(pred, out);
}

// round 4
// speedup vs baseline: 1.3720x; 1.3058x over previous
#include <cuda_runtime.h>
#include <cuda_bf16.h>
#include <math.h>

// predictions [16,1,512,512] f32, targets [16,1,512,512] i32, output scalar f32.
#define NIMG 16
#define H 512
#define W 512
#define NPIX (NIMG * H * W)
#define NBLK 2048          // colpass block count
#define IINF (1 << 20)
#define HALO 32
#define SROWS 128          // 64 tile rows + 2*HALO

// Packed per-pixel word: bits[0:16)=gb (1D dist to nearest BG site, clamped 1024),
// bits[16:31)=gf (1D dist to nearest FG site, clamped 1024), bit31 = target.
__device__ unsigned g_pk[NIMG * H * W];
__device__ double g_part[NBLK][5];
__device__ int g_ticket;

// One warp per row; each thread owns 16 CONTIGUOUS pixels.
__global__ void k_rowpass(const int* __restrict__ tg) {
    if (blockIdx.x == 0 && threadIdx.x == 0) g_ticket = 0;
    const int warp = threadIdx.x >> 5, lane = threadIdx.x & 31;
    const int row = blockIdx.x * 4 + warp;           // 8192 rows total
    const unsigned FULL = 0xFFFFFFFFu;

    const int4* tr = (const int4*)(tg + (size_t)row * W) + lane * 4;
    int m = 0;
    {
        int4 a = tr[0], b4 = tr[1], c = tr[2], d = tr[3];
        int v[16] = {a.x, a.y, a.z, a.w, b4.x, b4.y, b4.z, b4.w,
                     c.x, c.y, c.z, c.w, d.x, d.y, d.z, d.w};
#pragma unroll
        for (int j = 0; j < 16; j++) m |= (v[j] != 0) << j;
    }
    const int pbase = lane * 16;

    int laf[16], lab[16];
    int rf = IINF, rb = IINF;
#pragma unroll
    for (int j = 0; j < 16; j++) {
        int p = pbase + j;
        int bit = (m >> j) & 1;
        rf = min(rf, bit ? -p : IINF);
        rb = min(rb, bit ? IINF : -p);
        laf[j] = rf; lab[j] = rb;
    }
    int vf = rf, vb = rb;
#pragma unroll
    for (int o = 1; o < 32; o <<= 1) {
        int nf = __shfl_up_sync(FULL, vf, o);
        int nb = __shfl_up_sync(FULL, vb, o);
        if (lane >= o) { vf = min(vf, nf); vb = min(vb, nb); }
    }
    int ef = __shfl_up_sync(FULL, vf, 1); if (lane == 0) ef = IINF;
    int eb = __shfl_up_sync(FULL, vb, 1); if (lane == 0) eb = IINF;
#pragma unroll
    for (int j = 0; j < 16; j++) {
        int p = pbase + j;
        laf[j] = p + min(laf[j], ef);
        lab[j] = p + min(lab[j], eb);
    }

    int lbf[16], lbb[16];
    rf = IINF; rb = IINF;
#pragma unroll
    for (int j = 15; j >= 0; j--) {
        int p = pbase + j;
        int bit = (m >> j) & 1;
        rf = min(rf, bit ? p : IINF);
        rb = min(rb, bit ? IINF : p);
        lbf[j] = rf; lbb[j] = rb;
    }
    vf = rf; vb = rb;
#pragma unroll
    for (int o = 1; o < 32; o <<= 1) {
        int nf = __shfl_down_sync(FULL, vf, o);
        int nb = __shfl_down_sync(FULL, vb, o);
        if (lane + o < 32) { vf = min(vf, nf); vb = min(vb, nb); }
    }
    ef = __shfl_down_sync(FULL, vf, 1); if (lane == 31) ef = IINF;
    eb = __shfl_down_sync(FULL, vb, 1); if (lane == 31) eb = IINF;

    unsigned* outp = g_pk + (size_t)row * W + pbase;
#pragma unroll
    for (int q = 0; q < 4; q++) {
        unsigned tmp[4];
#pragma unroll
        for (int jj = 0; jj < 4; jj++) {
            int j = q * 4 + jj;
            int p = pbase + j;
            int Bf = -p + min(lbf[j], ef);
            int Bb = -p + min(lbb[j], eb);
            int gf = min(min(laf[j], Bf), 1024);
            int gb = min(min(lab[j], Bb), 1024);
            unsigned bit = (unsigned)((m >> j) & 1);
            tmp[jj] = (unsigned)gb | ((unsigned)gf << 16) | (bit << 31);
        }
        uint4 wv; wv.x = tmp[0]; wv.y = tmp[1]; wv.z = tmp[2]; wv.w = tmp[3];
        ((uint4*)outp)[q] = wv;
    }
}

// Column envelope out of SMEM tile (exact: global fallback past the halo),
// fused with sigmoid + partial sums and the grid-final ticketed reduction.
__global__ void k_colpass(const float* __restrict__ pred, float* __restrict__ out) {
    __shared__ unsigned shg[SROWS][32];
    __shared__ double shr[5][256];

    const int tx = threadIdx.x;
    const int x = blockIdx.x * 32 + tx;
    const int img = blockIdx.z;
    const int ybase0 = blockIdx.y * 64;
    const int ybase = ybase0 + threadIdx.y * 8;
    const unsigned* __restrict__ base = g_pk + (size_t)img * H * W;

    // cooperative tile load: rows [ybase0-HALO, ybase0+64+HALO), sentinel outside
    for (int r = threadIdx.y; r < SROWS; r += 8) {
        int gy = ybase0 - HALO + r;
        unsigned v = 0x7FFF7FFFu;
        if (gy >= 0 && gy < H) v = base[gy * W + x];
        shg[r][tx] = v;
    }
    __syncthreads();

    float s0 = 0.f, s1 = 0.f, s2 = 0.f, s3n = 0.f, s3p = 0.f;
#pragma unroll
    for (int k = 0; k < 8; k++) {
        const int y = ybase + k;
        const int yl = y - ybase0 + HALO;           // local row in tile
        const unsigned w = shg[yl][tx];
        const int tv = (int)(w >> 31);
        const int shn = tv ? 0 : 16;
        const unsigned msk = tv ? 0xFFFFu : 0x7FFFu;
        int g0 = (int)((w >> shn) & msk);
        float best = (float)(g0 * g0);
        for (int dy = 1; dy <= HALO; ++dy) {
            float dy2 = (float)(dy * dy);
            if (dy2 >= best) break;
            int gu = (int)((shg[yl - dy][tx] >> shn) & msk);
            int gd = (int)((shg[yl + dy][tx] >> shn) & msk);
            best = fminf(best, fminf((float)(gu * gu), (float)(gd * gd)) + dy2);
        }
        if (best > (float)(HALO * HALO)) {          // exact fallback (rare)
            for (int dy = HALO + 1; dy < H; ++dy) {
                float dy2 = (float)(dy * dy);
                if (dy2 >= best) break;
                int yu = y - dy, yd = y + dy;
                if (yu >= 0) {
                    int g = (int)((base[yu * W + x] >> shn) & msk);
                    best = fminf(best, (float)(g * g) + dy2);
                }
                if (yd < H) {
                    int g = (int)((base[yd * W + x] >> shn) & msk);
                    best = fminf(best, (float)(g * g) + dy2);
                }
            }
        }
        float pv = pred[(size_t)img * H * W + y * W + x];
        float p = 1.0f / (1.0f + __expf(-pv));
        float phi = sqrtf(best);
        s0 += p;
        s2 += (float)tv;
        if (tv) { s1 += p; s3n -= phi * p; }
        else    { s3p += phi * p; }
    }

    const int tid = threadIdx.y * 32 + tx;
    shr[0][tid] = (double)s0; shr[1][tid] = (double)s1; shr[2][tid] = (double)s2;
    shr[3][tid] = (double)s3n; shr[4][tid] = (double)s3p;
    __syncthreads();
    for (int o = 128; o > 0; o >>= 1) {
        if (tid < o) {
#pragma unroll
            for (int q = 0; q < 5; q++) shr[q][tid] += shr[q][tid + o];
        }
        __syncthreads();
    }

    const int bid = (blockIdx.z * gridDim.y + blockIdx.y) * gridDim.x + blockIdx.x;
    __shared__ int slast;
    if (tid == 0) {
#pragma unroll
        for (int q = 0; q < 5; q++) g_part[bid][q] = shr[q][0];
        __threadfence();
        slast = (atomicAdd(&g_ticket, 1) == NBLK - 1);
    }
    __syncthreads();
    if (!slast) return;
    __threadfence();

    // ---- last block: deterministic final reduction ----
    __shared__ double simg[NIMG];
    const int wid = tid >> 5, lane = tid & 31;
#pragma unroll
    for (int t = 0; t < 2; t++) {
        int im = wid * 2 + t;
        double s = 0;
        for (int e = lane; e < 128; e += 32) s += g_part[im * 128 + e][2];
#pragma unroll
        for (int o = 16; o > 0; o >>= 1) s += __shfl_down_sync(0xFFFFFFFFu, s, o);
        if (lane == 0) simg[im] = s;
    }
    __syncthreads();

    double a0 = 0, a1 = 0, a2 = 0, a3 = 0;
    for (int e = tid; e < NBLK; e += 256) {
        int im = e >> 7;
        double st = simg[im];
        bool anyfg = st > 0.0;
        bool anybg = st < (double)(H * W);
        a0 += g_part[e][0]; a1 += g_part[e][1]; a2 += g_part[e][2];
        if (anyfg) a3 += g_part[e][4] + (anybg ? g_part[e][3] : 0.0);
    }
    shr[0][tid] = a0; shr[1][tid] = a1; shr[2][tid] = a2; shr[3][tid] = a3;
    __syncthreads();
    for (int o = 128; o > 0; o >>= 1) {
        if (tid < o) {
#pragma unroll
            for (int q = 0; q < 4; q++) shr[q][tid] += shr[q][tid + o];
        }
        __syncthreads();
    }
    if (tid == 0) {
        double sum_p = shr[0][0], inter = shr[1][0], sum_t = shr[2][0], sb = shr[3][0];
        double smooth = 1e-06;
        double dice = 1.0 - (2.0 * inter + smooth) / (sum_p + sum_t + smooth);
        double loss = 0.99 * dice + 0.01 * (sb / (double)NPIX);
        out[0] = (float)loss;
    }
}

extern "C" void kernel_launch(void* const* d_in, const int* in_sizes, int n_in,
                              void* d_out, int out_size) {
    const float* pred = (const float*)d_in[0];
    const int*   targ = (const int*)d_in[1];
    float* out = (float*)d_out;

    k_rowpass<<<2048, 128>>>(targ);
    dim3 cb(32, 8, 1);
    dim3 cg(W / 32, H / 64, NIMG);   // 2048 blocks
    k_colpass<<<cg, cb>>>(pred, out);
}

// round 5
// speedup vs baseline: 1.5106x; 1.1011x over previous
#include <cuda_runtime.h>
#include <cuda_bf16.h>
#include <math.h>

// predictions [16,1,512,512] f32, targets [16,1,512,512] i32, output scalar f32.
#define NIMG 16
#define H 512
#define W 512
#define NPIX (NIMG * H * W)
#define NBLK 2048
#define IINF (1 << 20)
#define HALO 32
#define SROWS 128          // 64 tile rows + 2*HALO

// Packed per-pixel word: bits[0:16)=gb (1D dist to nearest BG site, clamped 1024),
// bits[16:31)=gf (1D dist to nearest FG site, clamped 1024), bit31 = target.
__device__ unsigned g_pk[NIMG * H * W];
__device__ double g_part[NBLK][5];
__device__ int g_ticket;

// One warp per row; each thread owns 16 CONTIGUOUS pixels.
__global__ void k_rowpass(const int* __restrict__ tg) {
    if (blockIdx.x == 0 && threadIdx.x == 0) g_ticket = 0;
    const int warp = threadIdx.x >> 5, lane = threadIdx.x & 31;
    const int row = blockIdx.x * 4 + warp;           // 8192 rows total
    const unsigned FULL = 0xFFFFFFFFu;

    const int4* tr = (const int4*)(tg + (size_t)row * W) + lane * 4;
    int m = 0;
    {
        int4 a = tr[0], b4 = tr[1], c = tr[2], d = tr[3];
        int v[16] = {a.x, a.y, a.z, a.w, b4.x, b4.y, b4.z, b4.w,
                     c.x, c.y, c.z, c.w, d.x, d.y, d.z, d.w};
#pragma unroll
        for (int j = 0; j < 16; j++) m |= (v[j] != 0) << j;
    }
    const int pbase = lane * 16;

    int laf[16], lab[16];
    int rf = IINF, rb = IINF;
#pragma unroll
    for (int j = 0; j < 16; j++) {
        int p = pbase + j;
        int bit = (m >> j) & 1;
        rf = min(rf, bit ? -p : IINF);
        rb = min(rb, bit ? IINF : -p);
        laf[j] = rf; lab[j] = rb;
    }
    int vf = rf, vb = rb;
#pragma unroll
    for (int o = 1; o < 32; o <<= 1) {
        int nf = __shfl_up_sync(FULL, vf, o);
        int nb = __shfl_up_sync(FULL, vb, o);
        if (lane >= o) { vf = min(vf, nf); vb = min(vb, nb); }
    }
    int ef = __shfl_up_sync(FULL, vf, 1); if (lane == 0) ef = IINF;
    int eb = __shfl_up_sync(FULL, vb, 1); if (lane == 0) eb = IINF;
#pragma unroll
    for (int j = 0; j < 16; j++) {
        int p = pbase + j;
        laf[j] = p + min(laf[j], ef);
        lab[j] = p + min(lab[j], eb);
    }

    int lbf[16], lbb[16];
    rf = IINF; rb = IINF;
#pragma unroll
    for (int j = 15; j >= 0; j--) {
        int p = pbase + j;
        int bit = (m >> j) & 1;
        rf = min(rf, bit ? p : IINF);
        rb = min(rb, bit ? IINF : p);
        lbf[j] = rf; lbb[j] = rb;
    }
    vf = rf; vb = rb;
#pragma unroll
    for (int o = 1; o < 32; o <<= 1) {
        int nf = __shfl_down_sync(FULL, vf, o);
        int nb = __shfl_down_sync(FULL, vb, o);
        if (lane + o < 32) { vf = min(vf, nf); vb = min(vb, nb); }
    }
    ef = __shfl_down_sync(FULL, vf, 1); if (lane == 31) ef = IINF;
    eb = __shfl_down_sync(FULL, vb, 1); if (lane == 31) eb = IINF;

    unsigned* outp = g_pk + (size_t)row * W + pbase;
#pragma unroll
    for (int q = 0; q < 4; q++) {
        unsigned tmp[4];
#pragma unroll
        for (int jj = 0; jj < 4; jj++) {
            int j = q * 4 + jj;
            int p = pbase + j;
            int Bf = -p + min(lbf[j], ef);
            int Bb = -p + min(lbb[j], eb);
            int gf = min(min(laf[j], Bf), 1024);
            int gb = min(min(lab[j], Bb), 1024);
            unsigned bit = (unsigned)((m >> j) & 1);
            tmp[jj] = (unsigned)gb | ((unsigned)gf << 16) | (bit << 31);
        }
        uint4 wv; wv.x = tmp[0]; wv.y = tmp[1]; wv.z = tmp[2]; wv.w = tmp[3];
        ((uint4*)outp)[q] = wv;
    }
}

// Column envelope from pre-squared SMEM tiles, chunked branch-free window,
// fused sigmoid + partial sums + ticketed grid-final reduction.
__global__ void k_colpass(const float* __restrict__ pred, float* __restrict__ out) {
    __shared__ float shf[SROWS * 32];   // g^2 to nearest FG site
    __shared__ float shb[SROWS * 32];   // g^2 to nearest BG site
    __shared__ unsigned sht[SROWS];     // target bits, one word per row (bit = tx)
    __shared__ double shr[5][8];

    const int tx = threadIdx.x;
    const int ty = threadIdx.y;
    const int x = blockIdx.x * 32 + tx;
    const int img = blockIdx.z;
    const int ybase0 = blockIdx.y * 64;
    const unsigned* __restrict__ base = g_pk + (size_t)img * H * W;

    // cooperative tile load + unpack; one warp per row (warp = fixed ty)
    for (int r = ty; r < SROWS; r += 8) {
        int gy = ybase0 - HALO + r;
        float vf = 1.0e9f, vb = 1.0e9f;
        unsigned tvbit = 0;
        if (gy >= 0 && gy < H) {
            unsigned w = base[gy * W + x];
            int gf = (int)((w >> 16) & 0x7FFFu);
            int gb = (int)(w & 0xFFFFu);
            vf = (float)(gf * gf);
            vb = (float)(gb * gb);
            tvbit = w >> 31;
        }
        shf[r * 32 + tx] = vf;
        shb[r * 32 + tx] = vb;
        unsigned bl = __ballot_sync(0xFFFFFFFFu, tvbit);
        if (tx == 0) sht[r] = bl;
    }
    __syncthreads();

    float s0 = 0.f, s1 = 0.f, s2 = 0.f, s3n = 0.f, s3p = 0.f;
#pragma unroll
    for (int k = 0; k < 8; k++) {
        const int yl = ty * 8 + k + HALO;           // local row in tile
        const int y = ybase0 + ty * 8 + k;
        const int tv = (int)((sht[yl] >> tx) & 1u);
        const float* __restrict__ col = (tv ? shb : shf) + tx;

        float best = col[yl * 32];
        // chunk 1: dy = 1..4
        {
            float m1 = fminf(col[(yl - 1) * 32], col[(yl + 1) * 32]) + 1.f;
            float m2 = fminf(col[(yl - 2) * 32], col[(yl + 2) * 32]) + 4.f;
            float m3 = fminf(col[(yl - 3) * 32], col[(yl + 3) * 32]) + 9.f;
            float m4 = fminf(col[(yl - 4) * 32], col[(yl + 4) * 32]) + 16.f;
            best = fminf(best, fminf(fminf(m1, m2), fminf(m3, m4)));
        }
        if (best > 25.f) {  // chunk 2: dy = 5..8
            float m1 = fminf(col[(yl - 5) * 32], col[(yl + 5) * 32]) + 25.f;
            float m2 = fminf(col[(yl - 6) * 32], col[(yl + 6) * 32]) + 36.f;
            float m3 = fminf(col[(yl - 7) * 32], col[(yl + 7) * 32]) + 49.f;
            float m4 = fminf(col[(yl - 8) * 32], col[(yl + 8) * 32]) + 64.f;
            best = fminf(best, fminf(fminf(m1, m2), fminf(m3, m4)));
            if (best > 81.f) {  // chunk 3: dy = 9..16
                float acc = best;
#pragma unroll
                for (int dy = 9; dy <= 16; dy++) {
                    float mm = fminf(col[(yl - dy) * 32], col[(yl + dy) * 32]) +
                               (float)(dy * dy);
                    acc = fminf(acc, mm);
                }
                best = acc;
                if (best > 289.f) {  // chunk 4: dy = 17..32
                    float a2 = best;
#pragma unroll
                    for (int dy = 17; dy <= 32; dy++) {
                        float mm = fminf(col[(yl - dy) * 32], col[(yl + dy) * 32]) +
                                   (float)(dy * dy);
                        a2 = fminf(a2, mm);
                    }
                    best = a2;
                    if (best > 1089.f) {  // exact fallback past halo (rare)
                        const int shn = tv ? 0 : 16;
                        const unsigned msk = tv ? 0xFFFFu : 0x7FFFu;
                        for (int dy = HALO + 1; dy < H; ++dy) {
                            float dy2 = (float)(dy * dy);
                            if (dy2 >= best) break;
                            int yu = y - dy, yd = y + dy;
                            if (yu >= 0) {
                                int g = (int)((base[yu * W + x] >> shn) & msk);
                                best = fminf(best, (float)(g * g) + dy2);
                            }
                            if (yd < H) {
                                int g = (int)((base[yd * W + x] >> shn) & msk);
                                best = fminf(best, (float)(g * g) + dy2);
                            }
                        }
                    }
                }
            }
        }

        float pv = pred[(size_t)img * H * W + y * W + x];
        float p = 1.0f / (1.0f + __expf(-pv));
        float phi = sqrtf(best);
        s0 += p;
        s2 += (float)tv;
        if (tv) { s1 += p; s3n -= phi * p; }
        else    { s3p += phi * p; }
    }

    // warp shuffle reduce, then tiny smem reduce over 8 warps
    const unsigned FULL = 0xFFFFFFFFu;
#pragma unroll
    for (int o = 16; o > 0; o >>= 1) {
        s0 += __shfl_down_sync(FULL, s0, o);
        s1 += __shfl_down_sync(FULL, s1, o);
        s2 += __shfl_down_sync(FULL, s2, o);
        s3n += __shfl_down_sync(FULL, s3n, o);
        s3p += __shfl_down_sync(FULL, s3p, o);
    }
    if (tx == 0) {
        shr[0][ty] = (double)s0; shr[1][ty] = (double)s1; shr[2][ty] = (double)s2;
        shr[3][ty] = (double)s3n; shr[4][ty] = (double)s3p;
    }
    __syncthreads();

    const int tid = ty * 32 + tx;
    const int bid = (blockIdx.z * gridDim.y + blockIdx.y) * gridDim.x + blockIdx.x;
    __shared__ int slast;
    if (tid == 0) {
#pragma unroll
        for (int q = 0; q < 5; q++) {
            double a = 0;
#pragma unroll
            for (int wgi = 0; wgi < 8; wgi++) a += shr[q][wgi];
            g_part[bid][q] = a;
        }
        __threadfence();
        slast = (atomicAdd(&g_ticket, 1) == NBLK - 1);
    }
    __syncthreads();
    if (!slast) return;
    __threadfence();

    // ---- last block: deterministic final reduction ----
    __shared__ double simg[NIMG];
    __shared__ double shfin[4][256];
    const int wid = tid >> 5, lane = tid & 31;
#pragma unroll
    for (int t = 0; t < 2; t++) {
        int im = wid * 2 + t;
        double s = 0;
        for (int e = lane; e < 128; e += 32) s += g_part[im * 128 + e][2];
#pragma unroll
        for (int o = 16; o > 0; o >>= 1) s += __shfl_down_sync(FULL, s, o);
        if (lane == 0) simg[im] = s;
    }
    __syncthreads();

    double a0 = 0, a1 = 0, a2 = 0, a3 = 0;
    for (int e = tid; e < NBLK; e += 256) {
        int im = e >> 7;
        double st = simg[im];
        bool anyfg = st > 0.0;
        bool anybg = st < (double)(H * W);
        a0 += g_part[e][0]; a1 += g_part[e][1]; a2 += g_part[e][2];
        if (anyfg) a3 += g_part[e][4] + (anybg ? g_part[e][3] : 0.0);
    }
    shfin[0][tid] = a0; shfin[1][tid] = a1; shfin[2][tid] = a2; shfin[3][tid] = a3;
    __syncthreads();
    for (int o = 128; o > 0; o >>= 1) {
        if (tid < o) {
#pragma unroll
            for (int q = 0; q < 4; q++) shfin[q][tid] += shfin[q][tid + o];
        }
        __syncthreads();
    }
    if (tid == 0) {
        double sum_p = shfin[0][0], inter = shfin[1][0], sum_t = shfin[2][0], sb = shfin[3][0];
        double smooth = 1e-06;
        double dice = 1.0 - (2.0 * inter + smooth) / (sum_p + sum_t + smooth);
        double loss = 0.99 * dice + 0.01 * (sb / (double)NPIX);
        out[0] = (float)loss;
    }
}

extern "C" void kernel_launch(void* const* d_in, const int* in_sizes, int n_in,
                              void* d_out, int out_size) {
    const float* pred = (const float*)d_in[0];
    const int*   targ = (const int*)d_in[1];
    float* out = (float*)d_out;

    k_rowpass<<<2048, 128>>>(targ);
    dim3 cb(32, 8, 1);
    dim3 cg(W / 32, H / 64, NIMG);   // 2048 blocks
    k_colpass<<<cg, cb>>>(pred, out);
}

// round 8
// speedup vs baseline: 1.7574x; 1.1634x over previous
#include <cuda_runtime.h>
#include <cuda_bf16.h>
#include <math.h>

// predictions [16,1,512,512] f32, targets [16,1,512,512] i32, output scalar f32.
#define NIMG 16
#define H 512
#define W 512
#define NPIX (NIMG * H * W)
#define NBLK 2048
#define IINF (1 << 20)
#define HALO 32
#define SROWS 128          // 64 tile rows + 2*HALO

// Float planes written by rowpass:
//  g_f2 = gf^2           (squared 1D dist to nearest FG site)  -- used by BG pixels
//  g_b2 = +/- gb^2       (squared 1D dist to nearest BG site; SIGN BIT = target)
__device__ float g_f2[NIMG * H * W];
__device__ float g_b2[NIMG * H * W];
__device__ double g_part[NBLK][5];
__device__ int g_ticket;

__device__ __forceinline__ float fsqrt_approx(float x) {
    float r;
    asm("sqrt.approx.f32 %0, %1;" : "=f"(r) : "f"(x));
    return r;
}
__device__ __forceinline__ float sigmoid_fast(float x) {
    float e, r;
    asm("ex2.approx.f32 %0, %1;" : "=f"(e) : "f"(-1.4426950408889634f * x));
    asm("rcp.approx.f32 %0, %1;" : "=f"(r) : "f"(1.0f + e));
    return r;
}

// One warp per row; each thread owns 16 CONTIGUOUS pixels.
__global__ void k_rowpass(const int* __restrict__ tg) {
    if (blockIdx.x == 0 && threadIdx.x == 0) g_ticket = 0;
    const int warp = threadIdx.x >> 5, lane = threadIdx.x & 31;
    const int row = blockIdx.x * 4 + warp;           // 8192 rows total
    const unsigned FULL = 0xFFFFFFFFu;

    const int4* tr = (const int4*)(tg + (size_t)row * W) + lane * 4;
    int m = 0;
    {
        int4 a = tr[0], b4 = tr[1], c = tr[2], d = tr[3];
        int v[16] = {a.x, a.y, a.z, a.w, b4.x, b4.y, b4.z, b4.w,
                     c.x, c.y, c.z, c.w, d.x, d.y, d.z, d.w};
#pragma unroll
        for (int j = 0; j < 16; j++) m |= (v[j] != 0) << j;
    }
    const int pbase = lane * 16;

    int laf[16], lab[16];
    int rf = IINF, rb = IINF;
#pragma unroll
    for (int j = 0; j < 16; j++) {
        int p = pbase + j;
        int bit = (m >> j) & 1;
        rf = min(rf, bit ? -p : IINF);
        rb = min(rb, bit ? IINF : -p);
        laf[j] = rf; lab[j] = rb;
    }
    int vf = rf, vb = rb;
#pragma unroll
    for (int o = 1; o < 32; o <<= 1) {
        int nf = __shfl_up_sync(FULL, vf, o);
        int nb = __shfl_up_sync(FULL, vb, o);
        if (lane >= o) { vf = min(vf, nf); vb = min(vb, nb); }
    }
    int ef = __shfl_up_sync(FULL, vf, 1); if (lane == 0) ef = IINF;
    int eb = __shfl_up_sync(FULL, vb, 1); if (lane == 0) eb = IINF;
#pragma unroll
    for (int j = 0; j < 16; j++) {
        int p = pbase + j;
        laf[j] = p + min(laf[j], ef);
        lab[j] = p + min(lab[j], eb);
    }

    int lbf[16], lbb[16];
    rf = IINF; rb = IINF;
#pragma unroll
    for (int j = 15; j >= 0; j--) {
        int p = pbase + j;
        int bit = (m >> j) & 1;
        rf = min(rf, bit ? p : IINF);
        rb = min(rb, bit ? IINF : p);
        lbf[j] = rf; lbb[j] = rb;
    }
    vf = rf; vb = rb;
#pragma unroll
    for (int o = 1; o < 32; o <<= 1) {
        int nf = __shfl_down_sync(FULL, vf, o);
        int nb = __shfl_down_sync(FULL, vb, o);
        if (lane + o < 32) { vf = min(vf, nf); vb = min(vb, nb); }
    }
    ef = __shfl_down_sync(FULL, vf, 1); if (lane == 31) ef = IINF;
    eb = __shfl_down_sync(FULL, vb, 1); if (lane == 31) eb = IINF;

    float* outf = g_f2 + (size_t)row * W + pbase;
    float* outb = g_b2 + (size_t)row * W + pbase;
#pragma unroll
    for (int q = 0; q < 4; q++) {
        float tf[4], tb[4];
#pragma unroll
        for (int jj = 0; jj < 4; jj++) {
            int j = q * 4 + jj;
            int p = pbase + j;
            int Bf = -p + min(lbf[j], ef);
            int Bb = -p + min(lbb[j], eb);
            int gf = min(min(laf[j], Bf), 1024);
            int gb = min(min(lab[j], Bb), 1024);
            float ff = (float)(gf * gf);
            float fb = (float)(gb * gb);
            int bit = (m >> j) & 1;
            tf[jj] = ff;
            tb[jj] = __int_as_float(__float_as_int(fb) | (bit << 31));
        }
        ((float4*)outf)[q] = make_float4(tf[0], tf[1], tf[2], tf[3]);
        ((float4*)outb)[q] = make_float4(tb[0], tb[1], tb[2], tb[3]);
    }
}

// Column envelope from pre-squared float SMEM tiles; warp-uniform escapes;
// fused sigmoid + partial sums + ticketed grid-final reduction.
__global__ void k_colpass(const float* __restrict__ pred, float* __restrict__ out) {
    __shared__ float sf[SROWS * 32];   // gf^2
    __shared__ float sb[SROWS * 32];   // +/- gb^2 (sign=target)
    __shared__ double shr[5][8];

    const int tx = threadIdx.x;
    const int ty = threadIdx.y;
    const int lane = tx;               // 32-wide warps, warp id = ty
    const int xblk = blockIdx.x * 32;
    const int x = xblk + tx;
    const int img = blockIdx.z;
    const int ybase0 = blockIdx.y * 64;
    const size_t ibase = (size_t)img * H * W;
    const unsigned FULL = 0xFFFFFFFFu;

    // ---- tile load: straight float4 copy, 4 rows per warp-iteration ----
    {
        const int seg = lane & 7;               // float4 segment within row
        const int rsub = lane >> 3;             // row within the 4-row group
        const float4* pf = (const float4*)(g_f2 + ibase);
        const float4* pb = (const float4*)(g_b2 + ibase);
        const int segbase = (xblk >> 2) + seg;
#pragma unroll
        for (int it = 0; it < 4; it++) {
            int r = it * 32 + ty * 4 + rsub;
            int gy = ybase0 - HALO + r;
            float4 vf4 = make_float4(1e9f, 1e9f, 1e9f, 1e9f);
            float4 vb4 = vf4;
            if (gy >= 0 && gy < H) {
                vf4 = pf[gy * (W / 4) + segbase];
                vb4 = pb[gy * (W / 4) + segbase];
            }
            ((float4*)sf)[r * 8 + seg] = vf4;
            ((float4*)sb)[r * 8 + seg] = vb4;
        }
    }

    // prefetch predictions (8 rows, stride W)
    float pv[8];
    {
        const float* pp = pred + ibase + (size_t)(ybase0 + ty * 8) * W + x;
#pragma unroll
        for (int k = 0; k < 8; k++) pv[k] = pp[k * W];
    }
    __syncthreads();

    float s0 = 0.f, s1 = 0.f, s2 = 0.f, s3n = 0.f, s3p = 0.f;
    const int cbase = (HALO + ty * 8) * 32 + tx;

#pragma unroll
    for (int k = 0; k < 8; k++) {
        const int ci = cbase + k * 32;
        const float cb = sb[ci];
        const float cf = sf[ci];
        const bool tv = cb < 0.0f;
        float best = tv ? -cb : cf;
        const float* col = (tv ? sb : sf) + ci;

        // chunk 1: dy = 1..4 (unconditional)
        {
            float m1 = fminf(fabsf(col[-1 * 32]), fabsf(col[1 * 32])) + 1.f;
            float m2 = fminf(fabsf(col[-2 * 32]), fabsf(col[2 * 32])) + 4.f;
            float m3 = fminf(fabsf(col[-3 * 32]), fabsf(col[3 * 32])) + 9.f;
            float m4 = fminf(fabsf(col[-4 * 32]), fabsf(col[4 * 32])) + 16.f;
            best = fminf(best, fminf(fminf(m1, m2), fminf(m3, m4)));
        }
        if (__any_sync(FULL, best > 25.f)) {          // dy = 5..16
            float acc = best;
#pragma unroll
            for (int dy = 5; dy <= 16; dy++) {
                float mm = fminf(fabsf(col[-dy * 32]), fabsf(col[dy * 32])) +
                           (float)(dy * dy);
                acc = fminf(acc, mm);
            }
            best = acc;
            if (__any_sync(FULL, best > 289.f)) {     // dy = 17..32
                float a2 = best;
#pragma unroll
                for (int dy = 17; dy <= 32; dy++) {
                    float mm = fminf(fabsf(col[-dy * 32]), fabsf(col[dy * 32])) +
                               (float)(dy * dy);
                    a2 = fminf(a2, mm);
                }
                best = a2;
                if (__any_sync(FULL, best > 1089.f)) {  // global fallback (rare)
                    const int y = ybase0 + ty * 8 + k;
                    const float* gcol = (tv ? g_b2 : g_f2) + ibase + x;
                    for (int dy = HALO + 1; dy < H; ++dy) {
                        float dy2 = (float)(dy * dy);
                        if (__all_sync(FULL, dy2 >= best)) break;
                        int yu = y - dy, yd = y + dy;
                        if (yu >= 0) best = fminf(best, fabsf(gcol[yu * W]) + dy2);
                        if (yd < H)  best = fminf(best, fabsf(gcol[yd * W]) + dy2);
                    }
                }
            }
        }

        float p = sigmoid_fast(pv[k]);
        float phi = fsqrt_approx(best);
        float pp = phi * p;
        s0 += p;
        if (tv) { s1 += p; s2 += 1.f; s3n -= pp; }
        else    { s3p += pp; }
    }

    // warp shuffle reduce, then tiny smem reduce over 8 warps
#pragma unroll
    for (int o = 16; o > 0; o >>= 1) {
        s0 += __shfl_down_sync(FULL, s0, o);
        s1 += __shfl_down_sync(FULL, s1, o);
        s2 += __shfl_down_sync(FULL, s2, o);
        s3n += __shfl_down_sync(FULL, s3n, o);
        s3p += __shfl_down_sync(FULL, s3p, o);
    }
    if (tx == 0) {
        shr[0][ty] = (double)s0; shr[1][ty] = (double)s1; shr[2][ty] = (double)s2;
        shr[3][ty] = (double)s3n; shr[4][ty] = (double)s3p;
    }
    __syncthreads();

    const int tid = ty * 32 + tx;
    const int bid = (blockIdx.z * gridDim.y + blockIdx.y) * gridDim.x + blockIdx.x;
    __shared__ int slast;
    if (tid == 0) {
#pragma unroll
        for (int q = 0; q < 5; q++) {
            double a = 0;
#pragma unroll
            for (int wgi = 0; wgi < 8; wgi++) a += shr[q][wgi];
            g_part[bid][q] = a;
        }
        __threadfence();
        slast = (atomicAdd(&g_ticket, 1) == NBLK - 1);
    }
    __syncthreads();
    if (!slast) return;
    __threadfence();

    // ---- last block: deterministic final reduction ----
    __shared__ double simg[NIMG];
    __shared__ double shfin[4][256];
    const int wid = tid >> 5, ln = tid & 31;
#pragma unroll
    for (int t = 0; t < 2; t++) {
        int im = wid * 2 + t;
        double s = 0;
        for (int e = ln; e < 128; e += 32) s += g_part[im * 128 + e][2];
#pragma unroll
        for (int o = 16; o > 0; o >>= 1) s += __shfl_down_sync(FULL, s, o);
        if (ln == 0) simg[im] = s;
    }
    __syncthreads();

    double a0 = 0, a1 = 0, a2 = 0, a3 = 0;
    for (int e = tid; e < NBLK; e += 256) {
        int im = e >> 7;
        double st = simg[im];
        bool anyfg = st > 0.0;
        bool anybg = st < (double)(H * W);
        a0 += g_part[e][0]; a1 += g_part[e][1]; a2 += g_part[e][2];
        if (anyfg) a3 += g_part[e][4] + (anybg ? g_part[e][3] : 0.0);
    }
    shfin[0][tid] = a0; shfin[1][tid] = a1; shfin[2][tid] = a2; shfin[3][tid] = a3;
    __syncthreads();
    for (int o = 128; o > 0; o >>= 1) {
        if (tid < o) {
#pragma unroll
            for (int q = 0; q < 4; q++) shfin[q][tid] += shfin[q][tid + o];
        }
        __syncthreads();
    }
    if (tid == 0) {
        double sum_p = shfin[0][0], inter = shfin[1][0], sum_t = shfin[2][0], sb_ = shfin[3][0];
        double smooth = 1e-06;
        double dice = 1.0 - (2.0 * inter + smooth) / (sum_p + sum_t + smooth);
        double loss = 0.99 * dice + 0.01 * (sb_ / (double)NPIX);
        out[0] = (float)loss;
    }
}

extern "C" void kernel_launch(void* const* d_in, const int* in_sizes, int n_in,
                              void* d_out, int out_size) {
    const float* pred = (const float*)d_in[0];
    const int*   targ = (const int*)d_in[1];
    float* out = (float*)d_out;

    k_rowpass<<<2048, 128>>>(targ);
    dim3 cb(32, 8, 1);
    dim3 cg(W / 32, H / 64, NIMG);   // 2048 blocks
    k_colpass<<<cg, cb>>>(pred, out);
}

// round 9
// speedup vs baseline: 1.8466x; 1.0507x over previous
#include <cuda_runtime.h>
#include <cuda_bf16.h>
#include <math.h>

// predictions [16,1,512,512] f32, targets [16,1,512,512] i32, output scalar f32.
#define NIMG 16
#define H 512
#define W 512
#define NPIX (NIMG * H * W)
#define NBLK 2048
#define IINF (1 << 20)
#define HALO 16
#define SROWS 96           // 64 tile rows + 2*HALO

// Float planes written by rowpass:
//  g_f2 = gf^2           (squared 1D dist to nearest FG site)  -- used by BG pixels
//  g_b2 = +/- gb^2       (squared 1D dist to nearest BG site; SIGN BIT = target)
__device__ float g_f2[NIMG * H * W];
__device__ float g_b2[NIMG * H * W];
__device__ double g_part[NBLK][5];
__device__ int g_ticket;

__device__ __forceinline__ float fsqrt_approx(float x) {
    float r;
    asm("sqrt.approx.f32 %0, %1;" : "=f"(r) : "f"(x));
    return r;
}
__device__ __forceinline__ float sigmoid_fast(float x) {
    float e, r;
    asm("ex2.approx.f32 %0, %1;" : "=f"(e) : "f"(-1.4426950408889634f * x));
    asm("rcp.approx.f32 %0, %1;" : "=f"(r) : "f"(1.0f + e));
    return r;
}

// One warp per row; each thread owns 16 CONTIGUOUS pixels.
__global__ void k_rowpass(const int* __restrict__ tg) {
    if (blockIdx.x == 0 && threadIdx.x == 0) g_ticket = 0;
    const int warp = threadIdx.x >> 5, lane = threadIdx.x & 31;
    const int row = blockIdx.x * 4 + warp;           // 8192 rows total
    const unsigned FULL = 0xFFFFFFFFu;

    const int4* tr = (const int4*)(tg + (size_t)row * W) + lane * 4;
    int m = 0;
    {
        int4 a = tr[0], b4 = tr[1], c = tr[2], d = tr[3];
        int v[16] = {a.x, a.y, a.z, a.w, b4.x, b4.y, b4.z, b4.w,
                     c.x, c.y, c.z, c.w, d.x, d.y, d.z, d.w};
#pragma unroll
        for (int j = 0; j < 16; j++) m |= (v[j] != 0) << j;
    }
    const int pbase = lane * 16;

    int laf[16], lab[16];
    int rf = IINF, rb = IINF;
#pragma unroll
    for (int j = 0; j < 16; j++) {
        int p = pbase + j;
        int bit = (m >> j) & 1;
        rf = min(rf, bit ? -p : IINF);
        rb = min(rb, bit ? IINF : -p);
        laf[j] = rf; lab[j] = rb;
    }
    int vf = rf, vb = rb;
#pragma unroll
    for (int o = 1; o < 32; o <<= 1) {
        int nf = __shfl_up_sync(FULL, vf, o);
        int nb = __shfl_up_sync(FULL, vb, o);
        if (lane >= o) { vf = min(vf, nf); vb = min(vb, nb); }
    }
    int ef = __shfl_up_sync(FULL, vf, 1); if (lane == 0) ef = IINF;
    int eb = __shfl_up_sync(FULL, vb, 1); if (lane == 0) eb = IINF;
#pragma unroll
    for (int j = 0; j < 16; j++) {
        int p = pbase + j;
        laf[j] = p + min(laf[j], ef);
        lab[j] = p + min(lab[j], eb);
    }

    int lbf[16], lbb[16];
    rf = IINF; rb = IINF;
#pragma unroll
    for (int j = 15; j >= 0; j--) {
        int p = pbase + j;
        int bit = (m >> j) & 1;
        rf = min(rf, bit ? p : IINF);
        rb = min(rb, bit ? IINF : p);
        lbf[j] = rf; lbb[j] = rb;
    }
    vf = rf; vb = rb;
#pragma unroll
    for (int o = 1; o < 32; o <<= 1) {
        int nf = __shfl_down_sync(FULL, vf, o);
        int nb = __shfl_down_sync(FULL, vb, o);
        if (lane + o < 32) { vf = min(vf, nf); vb = min(vb, nb); }
    }
    ef = __shfl_down_sync(FULL, vf, 1); if (lane == 31) ef = IINF;
    eb = __shfl_down_sync(FULL, vb, 1); if (lane == 31) eb = IINF;

    float* outf = g_f2 + (size_t)row * W + pbase;
    float* outb = g_b2 + (size_t)row * W + pbase;
#pragma unroll
    for (int q = 0; q < 4; q++) {
        float tf[4], tb[4];
#pragma unroll
        for (int jj = 0; jj < 4; jj++) {
            int j = q * 4 + jj;
            int p = pbase + j;
            int Bf = -p + min(lbf[j], ef);
            int Bb = -p + min(lbb[j], eb);
            int gf = min(min(laf[j], Bf), 1024);
            int gb = min(min(lab[j], Bb), 1024);
            float ff = (float)(gf * gf);
            float fb = (float)(gb * gb);
            int bit = (m >> j) & 1;
            tf[jj] = ff;
            tb[jj] = __int_as_float(__float_as_int(fb) | (bit << 31));
        }
        ((float4*)outf)[q] = make_float4(tf[0], tf[1], tf[2], tf[3]);
        ((float4*)outb)[q] = make_float4(tb[0], tb[1], tb[2], tb[3]);
    }
}

// Column envelope from pre-squared float SMEM tiles; warp-uniform escapes;
// fused sigmoid + partial sums + ticketed grid-final reduction.
__global__ void __launch_bounds__(256, 8)
k_colpass(const float* __restrict__ pred, float* __restrict__ out) {
    __shared__ float sf[SROWS * 32];   // gf^2
    __shared__ float sb[SROWS * 32];   // +/- gb^2 (sign=target)
    __shared__ double shr[5][8];

    const int tx = threadIdx.x;
    const int ty = threadIdx.y;
    const int xblk = blockIdx.x * 32;
    const int x = xblk + tx;
    const int img = blockIdx.z;
    const int ybase0 = blockIdx.y * 64;
    const size_t ibase = (size_t)img * H * W;
    const unsigned FULL = 0xFFFFFFFFu;

    // ---- tile load: straight float4 copy; 4 rows per warp per iteration ----
    {
        const int seg = tx & 7;                 // float4 segment within row
        const int rsub = tx >> 3;               // row within the 4-row group
        const float4* pf = (const float4*)(g_f2 + ibase);
        const float4* pb = (const float4*)(g_b2 + ibase);
        const int segbase = (xblk >> 2) + seg;
#pragma unroll
        for (int it = 0; it < 3; it++) {        // 3*32 = 96 rows
            int r = it * 32 + ty * 4 + rsub;
            int gy = ybase0 - HALO + r;
            float4 vf4 = make_float4(1e9f, 1e9f, 1e9f, 1e9f);
            float4 vb4 = vf4;
            if (gy >= 0 && gy < H) {
                vf4 = pf[gy * (W / 4) + segbase];
                vb4 = pb[gy * (W / 4) + segbase];
            }
            ((float4*)sf)[r * 8 + seg] = vf4;
            ((float4*)sb)[r * 8 + seg] = vb4;
        }
    }

    // prefetch predictions (8 rows, stride W)
    float pv[8];
    {
        const float* pp = pred + ibase + (size_t)(ybase0 + ty * 8) * W + x;
#pragma unroll
        for (int k = 0; k < 8; k++) pv[k] = pp[k * W];
    }
    __syncthreads();

    float s0 = 0.f, s1 = 0.f, s2 = 0.f, s3n = 0.f, s3p = 0.f;
    const int cbase = (HALO + ty * 8) * 32 + tx;

#pragma unroll
    for (int k = 0; k < 8; k++) {
        const int ci = cbase + k * 32;
        const float cb = sb[ci];
        const float cf = sf[ci];
        const bool tv = cb < 0.0f;
        float best = tv ? -cb : cf;
        const float* col = (tv ? sb : sf) + ci;

        // chunk 1: dy = 1..4 (unconditional)
        {
            float m1 = fminf(fabsf(col[-1 * 32]), fabsf(col[1 * 32])) + 1.f;
            float m2 = fminf(fabsf(col[-2 * 32]), fabsf(col[2 * 32])) + 4.f;
            float m3 = fminf(fabsf(col[-3 * 32]), fabsf(col[3 * 32])) + 9.f;
            float m4 = fminf(fabsf(col[-4 * 32]), fabsf(col[4 * 32])) + 16.f;
            best = fminf(best, fminf(fminf(m1, m2), fminf(m3, m4)));
        }
        if (__any_sync(FULL, best > 25.f)) {          // dy = 5..16 (within halo)
            float acc = best;
#pragma unroll
            for (int dy = 5; dy <= 16; dy++) {
                float mm = fminf(fabsf(col[-dy * 32]), fabsf(col[dy * 32])) +
                           (float)(dy * dy);
                acc = fminf(acc, mm);
            }
            best = acc;
            if (__any_sync(FULL, best > 289.f)) {     // global fallback (never on real data)
                const int y = ybase0 + ty * 8 + k;
                const float* gcol = (tv ? g_b2 : g_f2) + ibase + x;
                for (int dy = HALO + 1; dy < H; ++dy) {
                    float dy2 = (float)(dy * dy);
                    if (__all_sync(FULL, dy2 >= best)) break;
                    int yu = y - dy, yd = y + dy;
                    if (yu >= 0) best = fminf(best, fabsf(gcol[yu * W]) + dy2);
                    if (yd < H)  best = fminf(best, fabsf(gcol[yd * W]) + dy2);
                }
            }
        }

        float p = sigmoid_fast(pv[k]);
        float phi = fsqrt_approx(best);
        float pp = phi * p;
        s0 += p;
        if (tv) { s1 += p; s2 += 1.f; s3n -= pp; }
        else    { s3p += pp; }
    }

    // warp shuffle reduce, then tiny smem reduce over 8 warps
#pragma unroll
    for (int o = 16; o > 0; o >>= 1) {
        s0 += __shfl_down_sync(FULL, s0, o);
        s1 += __shfl_down_sync(FULL, s1, o);
        s2 += __shfl_down_sync(FULL, s2, o);
        s3n += __shfl_down_sync(FULL, s3n, o);
        s3p += __shfl_down_sync(FULL, s3p, o);
    }
    if (tx == 0) {
        shr[0][ty] = (double)s0; shr[1][ty] = (double)s1; shr[2][ty] = (double)s2;
        shr[3][ty] = (double)s3n; shr[4][ty] = (double)s3p;
    }
    __syncthreads();

    const int tid = ty * 32 + tx;
    const int bid = (blockIdx.z * gridDim.y + blockIdx.y) * gridDim.x + blockIdx.x;
    __shared__ int slast;
    if (tid == 0) {
#pragma unroll
        for (int q = 0; q < 5; q++) {
            double a = 0;
#pragma unroll
            for (int wgi = 0; wgi < 8; wgi++) a += shr[q][wgi];
            g_part[bid][q] = a;
        }
        __threadfence();
        slast = (atomicAdd(&g_ticket, 1) == NBLK - 1);
    }
    __syncthreads();
    if (!slast) return;
    __threadfence();

    // ---- last block: deterministic final reduction ----
    __shared__ double simg[NIMG];
    __shared__ double shfin[4][256];
    const int wid = tid >> 5, ln = tid & 31;
#pragma unroll
    for (int t = 0; t < 2; t++) {
        int im = wid * 2 + t;
        double s = 0;
        for (int e = ln; e < 128; e += 32) s += g_part[im * 128 + e][2];
#pragma unroll
        for (int o = 16; o > 0; o >>= 1) s += __shfl_down_sync(FULL, s, o);
        if (ln == 0) simg[im] = s;
    }
    __syncthreads();

    double a0 = 0, a1 = 0, a2 = 0, a3 = 0;
    for (int e = tid; e < NBLK; e += 256) {
        int im = e >> 7;
        double st = simg[im];
        bool anyfg = st > 0.0;
        bool anybg = st < (double)(H * W);
        a0 += g_part[e][0]; a1 += g_part[e][1]; a2 += g_part[e][2];
        if (anyfg) a3 += g_part[e][4] + (anybg ? g_part[e][3] : 0.0);
    }
    shfin[0][tid] = a0; shfin[1][tid] = a1; shfin[2][tid] = a2; shfin[3][tid] = a3;
    __syncthreads();
    for (int o = 128; o > 0; o >>= 1) {
        if (tid < o) {
#pragma unroll
            for (int q = 0; q < 4; q++) shfin[q][tid] += shfin[q][tid + o];
        }
        __syncthreads();
    }
    if (tid == 0) {
        double sum_p = shfin[0][0], inter = shfin[1][0], sum_t = shfin[2][0], sb_ = shfin[3][0];
        double smooth = 1e-06;
        double dice = 1.0 - (2.0 * inter + smooth) / (sum_p + sum_t + smooth);
        double loss = 0.99 * dice + 0.01 * (sb_ / (double)NPIX);
        out[0] = (float)loss;
    }
}

extern "C" void kernel_launch(void* const* d_in, const int* in_sizes, int n_in,
                              void* d_out, int out_size) {
    const float* pred = (const float*)d_in[0];
    const int*   targ = (const int*)d_in[1];
    float* out = (float*)d_out;

    k_rowpass<<<2048, 128>>>(targ);
    dim3 cb(32, 8, 1);
    dim3 cg(W / 32, H / 64, NIMG);   // 2048 blocks
    k_colpass<<<cg, cb>>>(pred, out);
}